// round 8
// baseline (speedup 1.0000x reference)
#include <cuda_runtime.h>
#include <cstdint>

// F=32, B=8192, D=64
// inputs: [F, B, 1, D] fp32 ; output: [B, D*D] fp32
// out[b, i*64+j] = s[b,i] * s[b,j], s = sum_f inputs[f,b,0,:]
//
// R8: emit the 16KB output tile per sample via one async bulk store
// (cp.async.bulk.global.shared::cta) instead of 32 warp STG.128s.
// Store issue leaves the warp pipeline; async engines stream dense 16KB
// writes to DRAM. Goal: raise dram__cycles_active from 59%.

#define F_DIM 32
#define B_DIM 8192
#define D_DIM 64
#define FB_STRIDE ((size_t)B_DIM * D_DIM)   // elements per field slab
#define OUT_TILE (D_DIM * D_DIM)            // 4096 floats = 16KB

__device__ __forceinline__ uint32_t smem_u32(const void* p) {
    uint32_t a;
    asm("{ .reg .u64 t; cvta.to.shared.u64 t, %1; cvt.u32.u64 %0, t; }"
        : "=r"(a) : "l"(p));
    return a;
}

__global__ __launch_bounds__(256, 8)
void opnn_kernel(const float* __restrict__ in, float* __restrict__ out) {
    const int b   = blockIdx.x;
    const int tid = threadIdx.x;      // 256 threads
    const int d   = tid & 63;         // 0..63
    const int g   = tid >> 6;         // 0..3 (field group of 8)

    __shared__ float partial[4][64];
    __shared__ float s[64];
    __shared__ __align__(128) float obuf[OUT_TILE];   // 16KB staging tile

    // Field-sum: each thread sums 8 fields for one d. Per-field access is a
    // contiguous 256B line across d (coalesced); 8 independent loads -> MLP.
    const float* base = in + (size_t)b * D_DIM + d + (size_t)(g * 8) * FB_STRIDE;
    float acc = 0.f;
#pragma unroll
    for (int k = 0; k < 8; k++)
        acc += __ldg(base + (size_t)k * FB_STRIDE);
    partial[g][d] = acc;
    __syncthreads();

    if (g == 0) {
        s[d] = partial[0][d] + partial[1][d] + partial[2][d] + partial[3][d];
    }
    __syncthreads();

    // Outer product into SMEM: 1024 float4 STS, conflict-free (consecutive
    // lanes hit consecutive banks).
    float4* ob4 = reinterpret_cast<float4*>(obuf);
    const float4* s4 = reinterpret_cast<const float4*>(s);
#pragma unroll
    for (int r = 0; r < 4; r++) {
        const int idx = tid + r * 256;   // float4 index 0..1023
        const int i   = idx >> 4;        // output row (16 float4 per row)
        const int jc  = idx & 15;        // column chunk
        const float  si = s[i];
        const float4 v  = s4[jc];
        float4 w;
        w.x = si * v.x;
        w.y = si * v.y;
        w.z = si * v.z;
        w.w = si * v.w;
        ob4[idx] = w;
    }
    __syncthreads();

    // One bulk async store: SMEM tile -> GMEM (16KB, async proxy).
    if (tid == 0) {
        float* gdst = out + (size_t)b * OUT_TILE;
        uint32_t src = smem_u32(obuf);
        asm volatile("fence.proxy.async.shared::cta;" ::: "memory");
        asm volatile(
            "cp.async.bulk.global.shared::cta.bulk_group [%0], [%1], %2;"
            :: "l"(gdst), "r"(src), "n"(OUT_TILE * 4) : "memory");
        asm volatile("cp.async.bulk.commit_group;" ::: "memory");
        // Hold the CTA alive until the engine has read SMEM; global-side
        // completion is covered by kernel-retire semantics.
        asm volatile("cp.async.bulk.wait_group.read 0;" ::: "memory");
    }
}

extern "C" void kernel_launch(void* const* d_in, const int* in_sizes, int n_in,
                              void* d_out, int out_size) {
    const float* in = (const float*)d_in[0];
    float* out = (float*)d_out;
    opnn_kernel<<<B_DIM, 256>>>(in, out);
}